// round 10
// baseline (speedup 1.0000x reference)
#include <cuda_runtime.h>
#include <math.h>

// ---------------- problem constants ----------------
#define BATCH 2
#define HH 256
#define WW_ 256
#define CC 180
#define C5 36
#define NHD 6
#define HD 15
#define L 256
#define ML 64
#define NWIN 512
#define PTOT (BATCH*HH*WW_)

typedef unsigned long long u64;

__device__ __forceinline__ u64 f2pack(float lo, float hi) {
    u64 r; asm("mov.b64 %0, {%1,%2};" : "=l"(r) : "f"(lo), "f"(hi)); return r;
}
__device__ __forceinline__ void f2unpack(u64 v, float& a, float& b) {
    asm("mov.b64 {%0,%1}, %2;" : "=f"(a), "=f"(b) : "l"(v));
}
__device__ __forceinline__ u64 f2fma(u64 a, u64 b, u64 c) {
    u64 d; asm("fma.rn.f32x2 %0, %1, %2, %3;" : "=l"(d) : "l"(a), "l"(b), "l"(c)); return d;
}
__device__ __forceinline__ float f2hadd(u64 v) {
    float a, b; f2unpack(v, a, b); return a + b;
}
__device__ __forceinline__ unsigned tf32r(float x) {
    unsigned r; asm("cvt.rna.tf32.f32 %0, %1;" : "=r"(r) : "f"(x)); return r;
}
__device__ __forceinline__ void mma8(float* c, unsigned a0, unsigned a1, unsigned a2, unsigned a3,
                                     unsigned b0, unsigned b1) {
    asm volatile(
        "mma.sync.aligned.m16n8k8.row.col.f32.tf32.tf32.f32 "
        "{%0,%1,%2,%3}, {%4,%5,%6,%7}, {%8,%9}, {%0,%1,%2,%3};"
        : "+f"(c[0]), "+f"(c[1]), "+f"(c[2]), "+f"(c[3])
        : "r"(a0), "r"(a1), "r"(a2), "r"(a3), "r"(b0), "r"(b1));
}

// ---------------- device scratch ----------------
__device__ float s_y1[PTOT * C5];
__device__ float s_y2[PTOT * C5];
__device__ float s_qv[PTOT * CC];
__device__ float s_cat[PTOT * CC];
__device__ float s_vp[NWIN * NHD * ML * HD];
__device__ float s_rpb[NHD * L * ML];   // layout: [n][m][l]  (transposed)
__device__ float s_tab[961 * NHD];

// ================= position-bias MLP table (961 x 6) =================
__global__ void k_postab(const float* __restrict__ pw, const float* __restrict__ pb,
                         const float* __restrict__ g1, const float* __restrict__ b1,
                         const float* __restrict__ m1w, const float* __restrict__ m1b,
                         const float* __restrict__ g2, const float* __restrict__ b2,
                         const float* __restrict__ m2w, const float* __restrict__ m2b,
                         const float* __restrict__ g3, const float* __restrict__ b3,
                         const float* __restrict__ m3w, const float* __restrict__ m3b) {
    int t = blockIdx.x * blockDim.x + threadIdx.x;
    if (t >= 961) return;
    int a = t / 31, bcol = t - a * 31;
    float gx = (float)a - 15.f, gy = (float)bcol - 15.f;
    float p[11], q[11];
#pragma unroll
    for (int j = 0; j < 11; j++) p[j] = gx * pw[j] + gy * pw[11 + j] + pb[j];
    {
        float m = 0.f;
#pragma unroll
        for (int j = 0; j < 11; j++) m += p[j];
        m *= (1.f / 11.f);
        float v = 0.f;
#pragma unroll
        for (int j = 0; j < 11; j++) { float d = p[j] - m; v += d * d; }
        v *= (1.f / 11.f);
        float inv = 1.f / sqrtf(v + 1e-5f);
#pragma unroll
        for (int j = 0; j < 11; j++) {
            float h = (p[j] - m) * inv * g1[j] + b1[j];
            q[j] = h > 0.f ? h : 0.f;
        }
#pragma unroll
        for (int j = 0; j < 11; j++) {
            float acc = m1b[j];
#pragma unroll
            for (int k = 0; k < 11; k++) acc += q[k] * m1w[k * 11 + j];
            p[j] = acc;
        }
    }
    {
        float m = 0.f;
#pragma unroll
        for (int j = 0; j < 11; j++) m += p[j];
        m *= (1.f / 11.f);
        float v = 0.f;
#pragma unroll
        for (int j = 0; j < 11; j++) { float d = p[j] - m; v += d * d; }
        v *= (1.f / 11.f);
        float inv = 1.f / sqrtf(v + 1e-5f);
#pragma unroll
        for (int j = 0; j < 11; j++) {
            float h = (p[j] - m) * inv * g2[j] + b2[j];
            q[j] = h > 0.f ? h : 0.f;
        }
#pragma unroll
        for (int j = 0; j < 11; j++) {
            float acc = m2b[j];
#pragma unroll
            for (int k = 0; k < 11; k++) acc += q[k] * m2w[k * 11 + j];
            p[j] = acc;
        }
    }
    {
        float m = 0.f;
#pragma unroll
        for (int j = 0; j < 11; j++) m += p[j];
        m *= (1.f / 11.f);
        float v = 0.f;
#pragma unroll
        for (int j = 0; j < 11; j++) { float d = p[j] - m; v += d * d; }
        v *= (1.f / 11.f);
        float inv = 1.f / sqrtf(v + 1e-5f);
#pragma unroll
        for (int j = 0; j < 11; j++) {
            float h = (p[j] - m) * inv * g3[j] + b3[j];
            q[j] = h > 0.f ? h : 0.f;
        }
#pragma unroll
        for (int n = 0; n < 6; n++) {
            float acc = m3b[n];
#pragma unroll
            for (int k = 0; k < 11; k++) acc += q[k] * m3w[k * 6 + n];
            s_tab[t * 6 + n] = acc;
        }
    }
}

// ================= rpb gather/average (writes transposed [n][m][l]) =================
__global__ void k_rpb() {
    int u = blockIdx.x * blockDim.x + threadIdx.x;
    int i = u >> 6, m = u & 63;
    int hi = i >> 4, wi = i & 15;
    int mh = m >> 3, mw = m & 7;
    float acc[6] = {0.f, 0.f, 0.f, 0.f, 0.f, 0.f};
#pragma unroll
    for (int rh = 0; rh < 2; rh++)
#pragma unroll
        for (int rw = 0; rw < 2; rw++) {
            int jh = mh * 2 + rh, jw = mw * 2 + rw;
            int idx = (hi - jh + 15) * 31 + (wi - jw + 15);
            const float* tr = s_tab + idx * 6;
#pragma unroll
            for (int n = 0; n < 6; n++) acc[n] += tr[n];
        }
#pragma unroll
    for (int n = 0; n < 6; n++) s_rpb[n * 16384 + m * 256 + i] = acc[n] * 0.25f;
}

// ================= DFE stage 1 (f32x2) =================
__global__ __launch_bounds__(256, 3) void k_dfe1(const float* __restrict__ x,
                                                 const float* __restrict__ w,
                                                 const float* __restrict__ b) {
    extern __shared__ float sm[];
    float* w1t = sm;              // 40*182
    float* xs  = sm + 40 * 182;   // 64*180
    int row0 = blockIdx.x * 64;
    int tid = threadIdx.x;
    for (int t = tid; t < 90 * 40; t += 256) {
        int kp = t / 40, c = t - kp * 40;
        float a = 0.f, bb = 0.f;
        if (c < 36) { a = w[(2 * kp) * 36 + c]; bb = w[(2 * kp + 1) * 36 + c]; }
        w1t[c * 182 + 2 * kp] = a;
        w1t[c * 182 + 2 * kp + 1] = bb;
    }
    {
        const float4* src = (const float4*)(x + row0 * 180);
        float4* dst = (float4*)xs;
        for (int t = tid; t < 64 * 45; t += 256) dst[t] = src[t];
    }
    __syncthreads();

    int tr = tid >> 3, tc = tid & 7;
    int r0 = tr * 2, c0 = tc * 5;
    u64 acc[2][5];
#pragma unroll
    for (int i = 0; i < 2; i++)
#pragma unroll
        for (int j = 0; j < 5; j++) acc[i][j] = 0ull;
    for (int kp = 0; kp < 90; kp++) {
        u64 av[2], bv[5];
#pragma unroll
        for (int i = 0; i < 2; i++) av[i] = *(const u64*)(xs + (r0 + i) * 180 + 2 * kp);
#pragma unroll
        for (int j = 0; j < 5; j++) bv[j] = *(const u64*)(w1t + (c0 + j) * 182 + 2 * kp);
#pragma unroll
        for (int i = 0; i < 2; i++)
#pragma unroll
            for (int j = 0; j < 5; j++) acc[i][j] = f2fma(av[i], bv[j], acc[i][j]);
    }
#pragma unroll
    for (int j = 0; j < 5; j++) {
        int c = c0 + j;
        if (c < 36) {
            float bc = b[c];
#pragma unroll
            for (int i = 0; i < 2; i++) {
                float v = f2hadd(acc[i][j]) + bc;
                s_y1[(row0 + r0 + i) * 36 + c] = v > 0.f ? v : 0.2f * v;
            }
        }
    }
}

// ================= DFE stage 2: 3x3 conv, f32x2 =================
__global__ __launch_bounds__(512, 1) void k_conv(const float* __restrict__ w,
                                                 const float* __restrict__ bias) {
    extern __shared__ float sm[];
    float2* hsp = (float2*)sm;                       // 18*324 f2
    float2* wt  = (float2*)(sm + 18 * 324 * 2);      // 9*18*40 f2
    int bImg = blockIdx.z, ty = blockIdx.y, tx = blockIdx.x;
    int tid = threadIdx.x;
    int y0 = ty * 16 - 1, x0 = tx * 16 - 1;

    for (int t = tid; t < 324 * 18; t += 512) {
        int hp = t / 18, kp = t - hp * 18;
        int py = hp / 18, px = hp - py * 18;
        int gy = y0 + py, gx = x0 + px;
        float2 v = make_float2(0.f, 0.f);
        if (gy >= 0 && gy < 256 && gx >= 0 && gx < 256)
            v = *(const float2*)(s_y1 + ((bImg * 256 + gy) * 256 + gx) * 36 + 2 * kp);
        hsp[kp * 324 + hp] = v;
    }
    for (int t = tid; t < 9 * 18 * 36; t += 512) {
        int tap = t / (18 * 36);
        int r = t - tap * (18 * 36);
        int kp = r / 36, c = r - kp * 36;
        int cg = c / 9, jc = c - cg * 9;
        wt[(tap * 18 + kp) * 40 + cg * 10 + jc] =
            make_float2(w[(tap * 36 + 2 * kp) * 36 + c], w[(tap * 36 + 2 * kp + 1) * 36 + c]);
    }
    __syncthreads();

    int cg = tid >> 7;
    int pp = tid & 127;
    int co0 = cg * 9;
    int p0 = pp, p1 = pp + 128;
    int hb0 = (p0 >> 4) * 18 + (p0 & 15);
    int hb1 = (p1 >> 4) * 18 + (p1 & 15);

    u64 acc[2][9];
#pragma unroll
    for (int ip = 0; ip < 2; ip++)
#pragma unroll
        for (int jc = 0; jc < 9; jc++) acc[ip][jc] = 0ull;

    for (int tap = 0; tap < 9; tap++) {
        int kh = tap / 3, kw = tap - 3 * kh;
        int off = kh * 18 + kw;
        const float2* wrow = wt + tap * 18 * 40 + cg * 10;
#pragma unroll 6
        for (int kp = 0; kp < 18; kp++) {
            u64 v0 = *(const u64*)(hsp + kp * 324 + hb0 + off);
            u64 v1 = *(const u64*)(hsp + kp * 324 + hb1 + off);
            const float2* wr = wrow + kp * 40;
            u64 wv[9];
#pragma unroll
            for (int jc = 0; jc < 9; jc++) wv[jc] = *(const u64*)(wr + jc);
#pragma unroll
            for (int jc = 0; jc < 9; jc++) {
                acc[0][jc] = f2fma(v0, wv[jc], acc[0][jc]);
                acc[1][jc] = f2fma(v1, wv[jc], acc[1][jc]);
            }
        }
    }

#pragma unroll
    for (int ip = 0; ip < 2; ip++) {
        int p = (ip == 0) ? p0 : p1;
        int py = p >> 4, px = p & 15;
        int gaddr = ((bImg * 256 + ty * 16 + py) * 256 + tx * 16 + px) * 36;
#pragma unroll
        for (int jc = 0; jc < 9; jc++) {
            float v = f2hadd(acc[ip][jc]) + bias[co0 + jc];
            s_y2[gaddr + co0 + jc] = v > 0.f ? v : 0.2f * v;
        }
    }
}

// ============ DFE stage 3 (PERSISTENT, f32x2, fused) ============
__global__ __launch_bounds__(512, 1) void k_dfe3(const float* __restrict__ x,
                                                 const float* __restrict__ w3, const float* __restrict__ b3,
                                                 const float* __restrict__ wl, const float* __restrict__ bl) {
    extern __shared__ float sm[];
    float* w3t = sm;                  // 192*38 floats
    float* wlt = w3t + 192 * 38;      // 192*182 floats
    float* xs  = wlt + 192 * 182;     // 64*180
    float* y2s = xs + 64 * 180;       // 64*36
    int tid = threadIdx.x;
    for (int t = tid; t < 192 * 19; t += 512) {
        int c = t / 19, kp = t - c * 19;
        float a = 0.f, bb = 0.f;
        if (c < 180 && kp < 18) { a = w3[(2 * kp) * 180 + c]; bb = w3[(2 * kp + 1) * 180 + c]; }
        w3t[2 * t] = a; w3t[2 * t + 1] = bb;
    }
    for (int t = tid; t < 192 * 91; t += 512) {
        int c = t / 91, kp = t - c * 91;
        float a = 0.f, bb = 0.f;
        if (c < 180 && kp < 90) { a = wl[(2 * kp) * 180 + c]; bb = wl[(2 * kp + 1) * 180 + c]; }
        wlt[2 * t] = a; wlt[2 * t + 1] = bb;
    }
    int warp = tid >> 5, lane = tid & 31;
    int r0 = warp * 4;
    int cidx[6]; float bcr[6], dcr[6];
#pragma unroll
    for (int j = 0; j < 6; j++) {
        int c = lane + 32 * j; cidx[j] = c;
        bcr[j] = (c < 180) ? b3[c] : 0.f;
        dcr[j] = (c < 180) ? bl[c] : 0.f;
    }

    for (int tile = blockIdx.x; tile < PTOT / 64; tile += gridDim.x) {
        int row0 = tile * 64;
        __syncthreads();
        {
            const float4* src = (const float4*)(x + row0 * 180);
            float4* dst = (float4*)xs;
            for (int t = tid; t < 64 * 45; t += 512) dst[t] = src[t];
            const float4* ys = (const float4*)(s_y2 + row0 * 36);
            float4* yd = (float4*)y2s;
            for (int t = tid; t < 64 * 9; t += 512) yd[t] = ys[t];
        }
        __syncthreads();

        u64 accA[4][6];
#pragma unroll
        for (int i = 0; i < 4; i++)
#pragma unroll
            for (int j = 0; j < 6; j++) accA[i][j] = 0ull;
        for (int kp = 0; kp < 18; kp++) {
            u64 av[4], bv[6];
#pragma unroll
            for (int i = 0; i < 4; i++) av[i] = *(const u64*)(y2s + (r0 + i) * 36 + 2 * kp);
#pragma unroll
            for (int j = 0; j < 6; j++) bv[j] = *(const u64*)(w3t + cidx[j] * 38 + 2 * kp);
#pragma unroll
            for (int i = 0; i < 4; i++)
#pragma unroll
                for (int j = 0; j < 6; j++) accA[i][j] = f2fma(av[i], bv[j], accA[i][j]);
        }
        float aA[4][6];
#pragma unroll
        for (int i = 0; i < 4; i++)
#pragma unroll
            for (int j = 0; j < 6; j++) aA[i][j] = f2hadd(accA[i][j]) + bcr[j];

        u64 accD[4][6];
#pragma unroll
        for (int i = 0; i < 4; i++)
#pragma unroll
            for (int j = 0; j < 6; j++) accD[i][j] = 0ull;
        for (int kp = 0; kp < 90; kp++) {
            u64 av[4], bv[6];
#pragma unroll
            for (int i = 0; i < 4; i++) av[i] = *(const u64*)(xs + (r0 + i) * 180 + 2 * kp);
#pragma unroll
            for (int j = 0; j < 6; j++) bv[j] = *(const u64*)(wlt + cidx[j] * 182 + 2 * kp);
#pragma unroll
            for (int i = 0; i < 4; i++)
#pragma unroll
                for (int j = 0; j < 6; j++) accD[i][j] = f2fma(av[i], bv[j], accD[i][j]);
        }
#pragma unroll
        for (int j = 0; j < 6; j++) {
            int c = cidx[j];
            if (c < 180) {
#pragma unroll
                for (int i = 0; i < 4; i++)
                    s_qv[(row0 + r0 + i) * 180 + c] = aA[i][j] * (f2hadd(accD[i][j]) + dcr[j]);
            }
        }
    }
}

// ================= vp: 16 lanes per entry (coalesced) =================
__global__ void k_vp(const float* __restrict__ sl_w, const float* __restrict__ sl_b) {
    int u = blockIdx.x * blockDim.x + threadIdx.x;
    if (u >= NWIN * 384 * 16) return;
    int c = u & 15;
    if (c >= 15) return;
    int v = u >> 4;
    int w = v / 384;
    int rem = v - w * 384;
    int n = rem >> 6, m = rem & 63;
    int b = w >> 8, wh = (w >> 4) & 15, ww = w & 15;
    int mh = m >> 3, mw = m & 7;
    int gh = wh * 16 + mh * 2, gw = ww * 16 + mw * 2;
    const float* q00 = s_qv + ((b * 256 + gh) * 256 + gw) * 180 + 90 + n * 15;
    float w0 = sl_w[0], w1 = sl_w[1], w2 = sl_w[2], w3 = sl_w[3], bb = sl_b[0];
    s_vp[v * 15 + c] = bb + q00[c] * w0 + q00[180 + c] * w1
                          + q00[256 * 180 + c] * w2 + q00[256 * 180 + 180 + c] * w3;
}

// ================= spatial correlation (f32x2, smem-staged I/O) =================
__global__ __launch_bounds__(256, 3) void k_sp() {
    __shared__ float vps[64 * 16];
    __shared__ float qs[256 * 17];
    int blk = blockIdx.x;
    int w = blk / 6, n = blk - w * 6;
    int b = w >> 8, wh = (w >> 4) & 15, ww = w & 15;
    int tid = threadIdx.x;
    const float* vsrc = s_vp + (w * 6 + n) * 960;
    for (int t = tid; t < 960; t += 256) {
        int m = t / 15, c = t - m * 15;
        vps[m * 16 + c] = vsrc[t];
    }
    if (tid < 64) vps[tid * 16 + 15] = 0.f;
    // coalesced q staging: 16 lanes per pixel
    for (int t = tid; t < 256 * 16; t += 256) {
        int pix = t >> 4, c = t & 15;
        if (c < 15) {
            int gh = wh * 16 + (pix >> 4), gw = ww * 16 + (pix & 15);
            qs[pix * 17 + c] = s_qv[((b * 256 + gh) * 256 + gw) * 180 + n * 15 + c];
        }
    }
    __syncthreads();

    int l = tid;
    float qr[15];
#pragma unroll
    for (int c = 0; c < 15; c++) qr[c] = qs[l * 17 + c];
    u64 qr2[8];
#pragma unroll
    for (int cp = 0; cp < 7; cp++) qr2[cp] = f2pack(qr[2 * cp], qr[2 * cp + 1]);
    qr2[7] = f2pack(qr[14], 0.f);

    u64 out2[8];
#pragma unroll
    for (int cp = 0; cp < 8; cp++) out2[cp] = 0ull;
    const float* rp = s_rpb + n * 16384;   // [m][l] layout

#pragma unroll
    for (int ch = 0; ch < 4; ch++) {
        float co[16];
#pragma unroll
        for (int mm = 0; mm < 16; mm++) {
            int m = ch * 16 + mm;
            u64 a = 0ull;
#pragma unroll
            for (int cp = 0; cp < 8; cp++)
                a = f2fma(qr2[cp], *(const u64*)(vps + m * 16 + 2 * cp), a);
            co[mm] = f2hadd(a) * (1.0f / 15.0f) + rp[m * 256 + l];
        }
#pragma unroll
        for (int mm = 0; mm < 16; mm++) {
            int m = ch * 16 + mm;
            u64 c2 = f2pack(co[mm], co[mm]);
#pragma unroll
            for (int cp = 0; cp < 8; cp++)
                out2[cp] = f2fma(c2, *(const u64*)(vps + m * 16 + 2 * cp), out2[cp]);
        }
    }
    // stage output into own qs row (each thread owns row l; reads of row l are done)
    float o[16];
#pragma unroll
    for (int cp = 0; cp < 8; cp++) f2unpack(out2[cp], o[2 * cp], o[2 * cp + 1]);
#pragma unroll
    for (int c = 0; c < 15; c++) qs[l * 17 + c] = o[c];
    __syncthreads();
    // coalesced writeback: 16 lanes per pixel
    for (int t = tid; t < 256 * 16; t += 256) {
        int pix = t >> 4, c = t & 15;
        if (c < 15) {
            int gh = wh * 16 + (pix >> 4), gw = ww * 16 + (pix & 15);
            s_cat[((b * 256 + gh) * 256 + gw) * 180 + n * 15 + c] = qs[pix * 17 + c];
        }
    }
}

// ================= channel correlation (f32x2) =================
#define QP 258
__global__ __launch_bounds__(512, 1) void k_ch() {
    extern __shared__ float sm[];
    float* q = sm;               // 186 * 258
    float* ccs = sm + 186 * QP;  // 90*90
    int w = blockIdx.x;
    int b = w >> 8, wh = (w >> 4) & 15, ww = w & 15;
    int tid = threadIdx.x;

    for (int t = tid; t < 6 * QP; t += 512) q[180 * QP + t] = 0.f;
    for (int t = tid; t < 256 * 45; t += 512) {
        int l = t / 45, j = t - l * 45;
        int gh = wh * 16 + (l >> 4), gw = ww * 16 + (l & 15);
        float4 v = *(const float4*)(s_qv + ((b * 256 + gh) * 256 + gw) * 180 + j * 4);
        int c = 4 * j;
        q[(c    ) * QP + l] = v.x;
        q[(c + 1) * QP + l] = v.y;
        q[(c + 2) * QP + l] = v.z;
        q[(c + 3) * QP + l] = v.w;
    }
    __syncthreads();

    {
        int wc = tid >> 5, td = tid & 31;
        u64 acc[6][3];
#pragma unroll
        for (int i = 0; i < 6; i++)
#pragma unroll
            for (int j = 0; j < 3; j++) acc[i][j] = 0ull;
        for (int lp = 0; lp < 128; lp++) {
            u64 qa[6], vb[3];
#pragma unroll
            for (int i = 0; i < 6; i++) qa[i] = *(const u64*)(q + (wc + 16 * i) * QP + 2 * lp);
#pragma unroll
            for (int j = 0; j < 3; j++) vb[j] = *(const u64*)(q + (90 + td + 32 * j) * QP + 2 * lp);
#pragma unroll
            for (int i = 0; i < 6; i++)
#pragma unroll
                for (int j = 0; j < 3; j++) acc[i][j] = f2fma(qa[i], vb[j], acc[i][j]);
        }
#pragma unroll
        for (int i = 0; i < 6; i++)
#pragma unroll
            for (int j = 0; j < 3; j++) {
                int c = wc + 16 * i, d = td + 32 * j;
                if (c < 90 && d < 90) ccs[c * 90 + d] = f2hadd(acc[i][j]) * (1.f / 256.f);
            }
    }
    __syncthreads();

    {
        int tl = tid & 31, wc = tid >> 5;
        int ci[6];
#pragma unroll
        for (int jc = 0; jc < 6; jc++) {
            int c = wc + 16 * jc;
            ci[jc] = (c < 90) ? c : 89;
        }
        u64 acc[4][6];
#pragma unroll
        for (int il = 0; il < 4; il++)
#pragma unroll
            for (int jc = 0; jc < 6; jc++) acc[il][jc] = 0ull;
        for (int d = 0; d < 90; d++) {
            u64 vv[4];
#pragma unroll
            for (int il = 0; il < 4; il++)
                vv[il] = *(const u64*)(q + (90 + d) * QP + 2 * (tl + 32 * il));
#pragma unroll
            for (int jc = 0; jc < 6; jc++) {
                float cv = ccs[ci[jc] * 90 + d];
                u64 cvp = f2pack(cv, cv);
#pragma unroll
                for (int il = 0; il < 4; il++) acc[il][jc] = f2fma(vv[il], cvp, acc[il][jc]);
            }
        }
#pragma unroll
        for (int jc = 0; jc < 6; jc++) {
            int c = wc + 16 * jc;
            if (c < 90) {
#pragma unroll
                for (int il = 0; il < 4; il++) {
                    int l0 = 2 * (tl + 32 * il);
                    float a0, a1;
                    f2unpack(acc[il][jc], a0, a1);
                    int gh0 = wh * 16 + (l0 >> 4), gw0 = ww * 16 + (l0 & 15);
                    s_cat[((b * 256 + gh0) * 256 + gw0) * 180 + 90 + c] = a0;
                    int l1 = l0 + 1;
                    int gh1 = wh * 16 + (l1 >> 4), gw1 = ww * 16 + (l1 & 15);
                    s_cat[((b * 256 + gh1) * 256 + gw1) * 180 + 90 + c] = a1;
                }
            }
        }
    }
}

// ============ k_projM: mma.sync tf32 GEMM  out = cat @ Wp + bp ============
#define KP 188
__global__ __launch_bounds__(256, 1) void k_projM(const float* __restrict__ wp,
                                                  const float* __restrict__ bp,
                                                  float* __restrict__ out) {
    extern __shared__ float sm[];
    float* As = sm;                  // 128*188
    float* Bs = As + 128 * KP;       // 64*188
    float* bias_s = Bs + 64 * KP;    // 192
    int tid = threadIdx.x;
    int row0 = blockIdx.x * 128;
    int wid = tid >> 5, lane = tid & 31;

    for (int t = tid; t < 192; t += 256) bias_s[t] = (t < 180) ? bp[t] : 0.f;
    for (int t = tid; t < 128 * 47; t += 256) {
        int r = t / 47, g = t - r * 47;
        unsigned* d = (unsigned*)(As + r * KP + 4 * g);
        if (g < 45) {
            float4 f = *(const float4*)(s_cat + (size_t)(row0 + r) * 180 + 4 * g);
            d[0] = tf32r(f.x); d[1] = tf32r(f.y); d[2] = tf32r(f.z); d[3] = tf32r(f.w);
        } else {
            d[0] = 0u; d[1] = 0u; d[2] = 0u; d[3] = 0u;
        }
    }

    int wm = wid * 16;
    int r1 = lane >> 2, kc = lane & 3;

#pragma unroll 1
    for (int nc = 0; nc < 3; nc++) {
        int nbase = nc * 64;
        __syncthreads();
        for (int t = tid; t < 47 * 64; t += 256) {
            int kq = t >> 6, n = t & 63;
            int col = nbase + n;
            unsigned v0 = 0u, v1 = 0u, v2 = 0u, v3 = 0u;
            if (col < 180) {
                int k = 4 * kq;
                if (k     < 180) v0 = tf32r(wp[(k    ) * 180 + col]);
                if (k + 1 < 180) v1 = tf32r(wp[(k + 1) * 180 + col]);
                if (k + 2 < 180) v2 = tf32r(wp[(k + 2) * 180 + col]);
                if (k + 3 < 180) v3 = tf32r(wp[(k + 3) * 180 + col]);
            }
            unsigned* d = (unsigned*)(Bs + n * KP + 4 * kq);
            d[0] = v0; d[1] = v1; d[2] = v2; d[3] = v3;
        }
        __syncthreads();

        float acc[8][4];
#pragma unroll
        for (int nf = 0; nf < 8; nf++)
#pragma unroll
            for (int j = 0; j < 4; j++) acc[nf][j] = 0.f;

        for (int ks = 0; ks < 23; ks++) {
            int k0 = ks * 8;
            const float* ar = As + (wm + r1) * KP + k0 + kc;
            unsigned a0 = *(const unsigned*)(ar);
            unsigned a1 = *(const unsigned*)(ar + 8 * KP);
            unsigned a2 = *(const unsigned*)(ar + 4);
            unsigned a3 = *(const unsigned*)(ar + 8 * KP + 4);
#pragma unroll
            for (int nf = 0; nf < 8; nf++) {
                const float* br = Bs + (nf * 8 + r1) * KP + k0 + kc;
                unsigned b0 = *(const unsigned*)(br);
                unsigned b1 = *(const unsigned*)(br + 4);
                mma8(acc[nf], a0, a1, a2, a3, b0, b1);
            }
        }

        int cb = 2 * (lane & 3);
#pragma unroll
        for (int nf = 0; nf < 8; nf++) {
            int col = nbase + nf * 8 + cb;
            if (col < 180) {
                int ro = row0 + wm + r1;
                float bx = bias_s[col], by = bias_s[col + 1];
                float2 v0 = make_float2(acc[nf][0] + bx, acc[nf][1] + by);
                *(float2*)(out + (size_t)ro * 180 + col) = v0;
                float2 v1 = make_float2(acc[nf][2] + bx, acc[nf][3] + by);
                *(float2*)(out + (size_t)(ro + 8) * 180 + col) = v1;
            }
        }
    }
}

// ================= launch =================
extern "C" void kernel_launch(void* const* d_in, const int* in_sizes, int n_in,
                              void* d_out, int out_size) {
    const float* x        = (const float*)d_in[0];
    const float* conv1_w  = (const float*)d_in[1];
    const float* conv1_b  = (const float*)d_in[2];
    const float* conv2_w  = (const float*)d_in[3];
    const float* conv2_b  = (const float*)d_in[4];
    const float* conv3_w  = (const float*)d_in[5];
    const float* conv3_b  = (const float*)d_in[6];
    const float* dfe_lw   = (const float*)d_in[7];
    const float* dfe_lb   = (const float*)d_in[8];
    const float* sl_w     = (const float*)d_in[9];
    const float* sl_b     = (const float*)d_in[10];
    const float* pos_w    = (const float*)d_in[11];
    const float* pos_b    = (const float*)d_in[12];
    const float* ln1_g    = (const float*)d_in[13];
    const float* ln1_b    = (const float*)d_in[14];
    const float* mlp1_w   = (const float*)d_in[15];
    const float* mlp1_b   = (const float*)d_in[16];
    const float* ln2_g    = (const float*)d_in[17];
    const float* ln2_b    = (const float*)d_in[18];
    const float* mlp2_w   = (const float*)d_in[19];
    const float* mlp2_b   = (const float*)d_in[20];
    const float* ln3_g    = (const float*)d_in[21];
    const float* ln3_b    = (const float*)d_in[22];
    const float* mlp3_w   = (const float*)d_in[23];
    const float* mlp3_b   = (const float*)d_in[24];
    const float* proj_w   = (const float*)d_in[25];
    const float* proj_b   = (const float*)d_in[26];
    float* out = (float*)d_out;

    const int SM1 = (40 * 182 + 64 * 180) * 4;
    const int SMCV = (18 * 324 * 2 + 9 * 18 * 40 * 2) * 4;
    const int SM3 = (192 * 38 + 192 * 182 + 64 * 180 + 64 * 36) * 4;
    const int SMC = (186 * QP + 90 * 90) * 4;
    const int SMPM = (128 * KP + 64 * KP + 192) * 4;

    cudaFuncSetAttribute(k_dfe1, cudaFuncAttributeMaxDynamicSharedMemorySize, SM1);
    cudaFuncSetAttribute(k_conv, cudaFuncAttributeMaxDynamicSharedMemorySize, SMCV);
    cudaFuncSetAttribute(k_dfe3, cudaFuncAttributeMaxDynamicSharedMemorySize, SM3);
    cudaFuncSetAttribute(k_ch,   cudaFuncAttributeMaxDynamicSharedMemorySize, SMC);
    cudaFuncSetAttribute(k_projM, cudaFuncAttributeMaxDynamicSharedMemorySize, SMPM);

    k_postab<<<4, 256>>>(pos_w, pos_b, ln1_g, ln1_b, mlp1_w, mlp1_b,
                         ln2_g, ln2_b, mlp2_w, mlp2_b, ln3_g, ln3_b, mlp3_w, mlp3_b);
    k_rpb<<<64, 256>>>();
    k_dfe1<<<PTOT / 64, 256, SM1>>>(x, conv1_w, conv1_b);
    k_conv<<<dim3(16, 16, 2), 512, SMCV>>>(conv2_w, conv2_b);
    k_dfe3<<<148, 512, SM3>>>(x, conv3_w, conv3_b, dfe_lw, dfe_lb);
    k_vp<<<(NWIN * 384 * 16 + 255) / 256, 256>>>(sl_w, sl_b);
    k_sp<<<NWIN * 6, 256>>>();
    k_ch<<<NWIN, 512, SMC>>>();
    k_projM<<<PTOT / 128, 256, SMPM>>>(proj_w, proj_b, out);
}

// round 12
// speedup vs baseline: 1.4744x; 1.4744x over previous
#include <cuda_runtime.h>
#include <math.h>

// ---------------- problem constants ----------------
#define BATCH 2
#define HH 256
#define WW_ 256
#define CC 180
#define C5 36
#define NHD 6
#define HD 15
#define L 256
#define ML 64
#define NWIN 512
#define PTOT (BATCH*HH*WW_)

typedef unsigned long long u64;

__device__ __forceinline__ u64 f2pack(float lo, float hi) {
    u64 r; asm("mov.b64 %0, {%1,%2};" : "=l"(r) : "f"(lo), "f"(hi)); return r;
}
__device__ __forceinline__ void f2unpack(u64 v, float& a, float& b) {
    asm("mov.b64 {%0,%1}, %2;" : "=f"(a), "=f"(b) : "l"(v));
}
__device__ __forceinline__ u64 f2fma(u64 a, u64 b, u64 c) {
    u64 d; asm("fma.rn.f32x2 %0, %1, %2, %3;" : "=l"(d) : "l"(a), "l"(b), "l"(c)); return d;
}
__device__ __forceinline__ float f2hadd(u64 v) {
    float a, b; f2unpack(v, a, b); return a + b;
}
__device__ __forceinline__ unsigned tf32r(float x) {
    unsigned r; asm("cvt.rna.tf32.f32 %0, %1;" : "=r"(r) : "f"(x)); return r;
}
__device__ __forceinline__ void mma8(float* c, unsigned a0, unsigned a1, unsigned a2, unsigned a3,
                                     unsigned b0, unsigned b1) {
    asm volatile(
        "mma.sync.aligned.m16n8k8.row.col.f32.tf32.tf32.f32 "
        "{%0,%1,%2,%3}, {%4,%5,%6,%7}, {%8,%9}, {%0,%1,%2,%3};"
        : "+f"(c[0]), "+f"(c[1]), "+f"(c[2]), "+f"(c[3])
        : "r"(a0), "r"(a1), "r"(a2), "r"(a3), "r"(b0), "r"(b1));
}

// ---------------- device scratch ----------------
__device__ float s_y1[PTOT * C5];
__device__ float s_y2[PTOT * C5];
__device__ float s_qv[PTOT * CC];
__device__ float s_cat[PTOT * CC];
__device__ float s_vp[NWIN * NHD * ML * HD];
__device__ float s_rpb[NHD * L * ML];   // layout: [n][m][l]  (transposed)
__device__ float s_tab[961 * NHD];

// ================= position-bias MLP table (961 x 6) =================
__global__ void k_postab(const float* __restrict__ pw, const float* __restrict__ pb,
                         const float* __restrict__ g1, const float* __restrict__ b1,
                         const float* __restrict__ m1w, const float* __restrict__ m1b,
                         const float* __restrict__ g2, const float* __restrict__ b2,
                         const float* __restrict__ m2w, const float* __restrict__ m2b,
                         const float* __restrict__ g3, const float* __restrict__ b3,
                         const float* __restrict__ m3w, const float* __restrict__ m3b) {
    int t = blockIdx.x * blockDim.x + threadIdx.x;
    if (t >= 961) return;
    int a = t / 31, bcol = t - a * 31;
    float gx = (float)a - 15.f, gy = (float)bcol - 15.f;
    float p[11], q[11];
#pragma unroll
    for (int j = 0; j < 11; j++) p[j] = gx * pw[j] + gy * pw[11 + j] + pb[j];
    {
        float m = 0.f;
#pragma unroll
        for (int j = 0; j < 11; j++) m += p[j];
        m *= (1.f / 11.f);
        float v = 0.f;
#pragma unroll
        for (int j = 0; j < 11; j++) { float d = p[j] - m; v += d * d; }
        v *= (1.f / 11.f);
        float inv = 1.f / sqrtf(v + 1e-5f);
#pragma unroll
        for (int j = 0; j < 11; j++) {
            float h = (p[j] - m) * inv * g1[j] + b1[j];
            q[j] = h > 0.f ? h : 0.f;
        }
#pragma unroll
        for (int j = 0; j < 11; j++) {
            float acc = m1b[j];
#pragma unroll
            for (int k = 0; k < 11; k++) acc += q[k] * m1w[k * 11 + j];
            p[j] = acc;
        }
    }
    {
        float m = 0.f;
#pragma unroll
        for (int j = 0; j < 11; j++) m += p[j];
        m *= (1.f / 11.f);
        float v = 0.f;
#pragma unroll
        for (int j = 0; j < 11; j++) { float d = p[j] - m; v += d * d; }
        v *= (1.f / 11.f);
        float inv = 1.f / sqrtf(v + 1e-5f);
#pragma unroll
        for (int j = 0; j < 11; j++) {
            float h = (p[j] - m) * inv * g2[j] + b2[j];
            q[j] = h > 0.f ? h : 0.f;
        }
#pragma unroll
        for (int j = 0; j < 11; j++) {
            float acc = m2b[j];
#pragma unroll
            for (int k = 0; k < 11; k++) acc += q[k] * m2w[k * 11 + j];
            p[j] = acc;
        }
    }
    {
        float m = 0.f;
#pragma unroll
        for (int j = 0; j < 11; j++) m += p[j];
        m *= (1.f / 11.f);
        float v = 0.f;
#pragma unroll
        for (int j = 0; j < 11; j++) { float d = p[j] - m; v += d * d; }
        v *= (1.f / 11.f);
        float inv = 1.f / sqrtf(v + 1e-5f);
#pragma unroll
        for (int j = 0; j < 11; j++) {
            float h = (p[j] - m) * inv * g3[j] + b3[j];
            q[j] = h > 0.f ? h : 0.f;
        }
#pragma unroll
        for (int n = 0; n < 6; n++) {
            float acc = m3b[n];
#pragma unroll
            for (int k = 0; k < 11; k++) acc += q[k] * m3w[k * 6 + n];
            s_tab[t * 6 + n] = acc;
        }
    }
}

// ================= rpb gather/average (transposed [n][m][l], l lane-fast stores) =================
__global__ void k_rpb() {
    int u = blockIdx.x * blockDim.x + threadIdx.x;  // < 16384
    int m = u >> 8, i = u & 255;                    // i = l (lane-fast), m = 0..63
    int hi = i >> 4, wi = i & 15;
    int mh = m >> 3, mw = m & 7;
    float acc[6] = {0.f, 0.f, 0.f, 0.f, 0.f, 0.f};
#pragma unroll
    for (int rh = 0; rh < 2; rh++)
#pragma unroll
        for (int rw = 0; rw < 2; rw++) {
            int jh = mh * 2 + rh, jw = mw * 2 + rw;
            int idx = (hi - jh + 15) * 31 + (wi - jw + 15);
            const float* tr = s_tab + idx * 6;
#pragma unroll
            for (int n = 0; n < 6; n++) acc[n] += tr[n];
        }
#pragma unroll
    for (int n = 0; n < 6; n++) s_rpb[n * 16384 + m * 256 + i] = acc[n] * 0.25f;
}

// ================= DFE stage 1 (f32x2) =================
__global__ __launch_bounds__(256, 3) void k_dfe1(const float* __restrict__ x,
                                                 const float* __restrict__ w,
                                                 const float* __restrict__ b) {
    extern __shared__ float sm[];
    float* w1t = sm;              // 40*182
    float* xs  = sm + 40 * 182;   // 64*180
    int row0 = blockIdx.x * 64;
    int tid = threadIdx.x;
    for (int t = tid; t < 90 * 40; t += 256) {
        int kp = t / 40, c = t - kp * 40;
        float a = 0.f, bb = 0.f;
        if (c < 36) { a = w[(2 * kp) * 36 + c]; bb = w[(2 * kp + 1) * 36 + c]; }
        w1t[c * 182 + 2 * kp] = a;
        w1t[c * 182 + 2 * kp + 1] = bb;
    }
    {
        const float4* src = (const float4*)(x + row0 * 180);
        float4* dst = (float4*)xs;
        for (int t = tid; t < 64 * 45; t += 256) dst[t] = src[t];
    }
    __syncthreads();

    int tr = tid >> 3, tc = tid & 7;
    int r0 = tr * 2, c0 = tc * 5;
    u64 acc[2][5];
#pragma unroll
    for (int i = 0; i < 2; i++)
#pragma unroll
        for (int j = 0; j < 5; j++) acc[i][j] = 0ull;
    for (int kp = 0; kp < 90; kp++) {
        u64 av[2], bv[5];
#pragma unroll
        for (int i = 0; i < 2; i++) av[i] = *(const u64*)(xs + (r0 + i) * 180 + 2 * kp);
#pragma unroll
        for (int j = 0; j < 5; j++) bv[j] = *(const u64*)(w1t + (c0 + j) * 182 + 2 * kp);
#pragma unroll
        for (int i = 0; i < 2; i++)
#pragma unroll
            for (int j = 0; j < 5; j++) acc[i][j] = f2fma(av[i], bv[j], acc[i][j]);
    }
#pragma unroll
    for (int j = 0; j < 5; j++) {
        int c = c0 + j;
        if (c < 36) {
            float bc = b[c];
#pragma unroll
            for (int i = 0; i < 2; i++) {
                float v = f2hadd(acc[i][j]) + bc;
                s_y1[(row0 + r0 + i) * 36 + c] = v > 0.f ? v : 0.2f * v;
            }
        }
    }
}

// ================= DFE stage 2: 3x3 conv, f32x2 =================
__global__ __launch_bounds__(512, 1) void k_conv(const float* __restrict__ w,
                                                 const float* __restrict__ bias) {
    extern __shared__ float sm[];
    float2* hsp = (float2*)sm;                       // 18*324 f2
    float2* wt  = (float2*)(sm + 18 * 324 * 2);      // 9*18*40 f2
    int bImg = blockIdx.z, ty = blockIdx.y, tx = blockIdx.x;
    int tid = threadIdx.x;
    int y0 = ty * 16 - 1, x0 = tx * 16 - 1;

    for (int t = tid; t < 324 * 18; t += 512) {
        int hp = t / 18, kp = t - hp * 18;
        int py = hp / 18, px = hp - py * 18;
        int gy = y0 + py, gx = x0 + px;
        float2 v = make_float2(0.f, 0.f);
        if (gy >= 0 && gy < 256 && gx >= 0 && gx < 256)
            v = *(const float2*)(s_y1 + ((bImg * 256 + gy) * 256 + gx) * 36 + 2 * kp);
        hsp[kp * 324 + hp] = v;
    }
    for (int t = tid; t < 9 * 18 * 36; t += 512) {
        int tap = t / (18 * 36);
        int r = t - tap * (18 * 36);
        int kp = r / 36, c = r - kp * 36;
        int cg = c / 9, jc = c - cg * 9;
        wt[(tap * 18 + kp) * 40 + cg * 10 + jc] =
            make_float2(w[(tap * 36 + 2 * kp) * 36 + c], w[(tap * 36 + 2 * kp + 1) * 36 + c]);
    }
    __syncthreads();

    int cg = tid >> 7;
    int pp = tid & 127;
    int co0 = cg * 9;
    int p0 = pp, p1 = pp + 128;
    int hb0 = (p0 >> 4) * 18 + (p0 & 15);
    int hb1 = (p1 >> 4) * 18 + (p1 & 15);

    u64 acc[2][9];
#pragma unroll
    for (int ip = 0; ip < 2; ip++)
#pragma unroll
        for (int jc = 0; jc < 9; jc++) acc[ip][jc] = 0ull;

    for (int tap = 0; tap < 9; tap++) {
        int kh = tap / 3, kw = tap - 3 * kh;
        int off = kh * 18 + kw;
        const float2* wrow = wt + tap * 18 * 40 + cg * 10;
#pragma unroll 6
        for (int kp = 0; kp < 18; kp++) {
            u64 v0 = *(const u64*)(hsp + kp * 324 + hb0 + off);
            u64 v1 = *(const u64*)(hsp + kp * 324 + hb1 + off);
            const float2* wr = wrow + kp * 40;
            u64 wv[9];
#pragma unroll
            for (int jc = 0; jc < 9; jc++) wv[jc] = *(const u64*)(wr + jc);
#pragma unroll
            for (int jc = 0; jc < 9; jc++) {
                acc[0][jc] = f2fma(v0, wv[jc], acc[0][jc]);
                acc[1][jc] = f2fma(v1, wv[jc], acc[1][jc]);
            }
        }
    }

#pragma unroll
    for (int ip = 0; ip < 2; ip++) {
        int p = (ip == 0) ? p0 : p1;
        int py = p >> 4, px = p & 15;
        int gaddr = ((bImg * 256 + ty * 16 + py) * 256 + tx * 16 + px) * 36;
#pragma unroll
        for (int jc = 0; jc < 9; jc++) {
            float v = f2hadd(acc[ip][jc]) + bias[co0 + jc];
            s_y2[gaddr + co0 + jc] = v > 0.f ? v : 0.2f * v;
        }
    }
}

// ============ DFE stage 3 (PERSISTENT, f32x2, fused) ============
__global__ __launch_bounds__(512, 1) void k_dfe3(const float* __restrict__ x,
                                                 const float* __restrict__ w3, const float* __restrict__ b3,
                                                 const float* __restrict__ wl, const float* __restrict__ bl) {
    extern __shared__ float sm[];
    float* w3t = sm;                  // 192*38 floats
    float* wlt = w3t + 192 * 38;      // 192*182 floats
    float* xs  = wlt + 192 * 182;     // 64*180
    float* y2s = xs + 64 * 180;       // 64*36
    int tid = threadIdx.x;
    for (int t = tid; t < 192 * 19; t += 512) {
        int c = t / 19, kp = t - c * 19;
        float a = 0.f, bb = 0.f;
        if (c < 180 && kp < 18) { a = w3[(2 * kp) * 180 + c]; bb = w3[(2 * kp + 1) * 180 + c]; }
        w3t[2 * t] = a; w3t[2 * t + 1] = bb;
    }
    for (int t = tid; t < 192 * 91; t += 512) {
        int c = t / 91, kp = t - c * 91;
        float a = 0.f, bb = 0.f;
        if (c < 180 && kp < 90) { a = wl[(2 * kp) * 180 + c]; bb = wl[(2 * kp + 1) * 180 + c]; }
        wlt[2 * t] = a; wlt[2 * t + 1] = bb;
    }
    int warp = tid >> 5, lane = tid & 31;
    int r0 = warp * 4;
    int cidx[6]; float bcr[6], dcr[6];
#pragma unroll
    for (int j = 0; j < 6; j++) {
        int c = lane + 32 * j; cidx[j] = c;
        bcr[j] = (c < 180) ? b3[c] : 0.f;
        dcr[j] = (c < 180) ? bl[c] : 0.f;
    }

    for (int tile = blockIdx.x; tile < PTOT / 64; tile += gridDim.x) {
        int row0 = tile * 64;
        __syncthreads();
        {
            const float4* src = (const float4*)(x + row0 * 180);
            float4* dst = (float4*)xs;
            for (int t = tid; t < 64 * 45; t += 512) dst[t] = src[t];
            const float4* ys = (const float4*)(s_y2 + row0 * 36);
            float4* yd = (float4*)y2s;
            for (int t = tid; t < 64 * 9; t += 512) yd[t] = ys[t];
        }
        __syncthreads();

        u64 accA[4][6];
#pragma unroll
        for (int i = 0; i < 4; i++)
#pragma unroll
            for (int j = 0; j < 6; j++) accA[i][j] = 0ull;
        for (int kp = 0; kp < 18; kp++) {
            u64 av[4], bv[6];
#pragma unroll
            for (int i = 0; i < 4; i++) av[i] = *(const u64*)(y2s + (r0 + i) * 36 + 2 * kp);
#pragma unroll
            for (int j = 0; j < 6; j++) bv[j] = *(const u64*)(w3t + cidx[j] * 38 + 2 * kp);
#pragma unroll
            for (int i = 0; i < 4; i++)
#pragma unroll
                for (int j = 0; j < 6; j++) accA[i][j] = f2fma(av[i], bv[j], accA[i][j]);
        }
        float aA[4][6];
#pragma unroll
        for (int i = 0; i < 4; i++)
#pragma unroll
            for (int j = 0; j < 6; j++) aA[i][j] = f2hadd(accA[i][j]) + bcr[j];

        u64 accD[4][6];
#pragma unroll
        for (int i = 0; i < 4; i++)
#pragma unroll
            for (int j = 0; j < 6; j++) accD[i][j] = 0ull;
        for (int kp = 0; kp < 90; kp++) {
            u64 av[4], bv[6];
#pragma unroll
            for (int i = 0; i < 4; i++) av[i] = *(const u64*)(xs + (r0 + i) * 180 + 2 * kp);
#pragma unroll
            for (int j = 0; j < 6; j++) bv[j] = *(const u64*)(wlt + cidx[j] * 182 + 2 * kp);
#pragma unroll
            for (int i = 0; i < 4; i++)
#pragma unroll
                for (int j = 0; j < 6; j++) accD[i][j] = f2fma(av[i], bv[j], accD[i][j]);
        }
#pragma unroll
        for (int j = 0; j < 6; j++) {
            int c = cidx[j];
            if (c < 180) {
#pragma unroll
                for (int i = 0; i < 4; i++)
                    s_qv[(row0 + r0 + i) * 180 + c] = aA[i][j] * (f2hadd(accD[i][j]) + dcr[j]);
            }
        }
    }
}

// ================= vp: 16 lanes per entry (coalesced) =================
__global__ void k_vp(const float* __restrict__ sl_w, const float* __restrict__ sl_b) {
    int u = blockIdx.x * blockDim.x + threadIdx.x;
    if (u >= NWIN * 384 * 16) return;
    int c = u & 15;
    if (c >= 15) return;
    int v = u >> 4;
    int w = v / 384;
    int rem = v - w * 384;
    int n = rem >> 6, m = rem & 63;
    int b = w >> 8, wh = (w >> 4) & 15, ww = w & 15;
    int mh = m >> 3, mw = m & 7;
    int gh = wh * 16 + mh * 2, gw = ww * 16 + mw * 2;
    const float* q00 = s_qv + ((b * 256 + gh) * 256 + gw) * 180 + 90 + n * 15;
    float w0 = sl_w[0], w1 = sl_w[1], w2 = sl_w[2], w3 = sl_w[3], bb = sl_b[0];
    s_vp[v * 15 + c] = bb + q00[c] * w0 + q00[180 + c] * w1
                          + q00[256 * 180 + c] * w2 + q00[256 * 180 + 180 + c] * w3;
}

// ================= spatial correlation (f32x2, smem-staged I/O) =================
__global__ __launch_bounds__(256, 3) void k_sp() {
    __shared__ float vps[64 * 16];
    __shared__ float qs[256 * 17];
    int blk = blockIdx.x;
    int w = blk / 6, n = blk - w * 6;
    int b = w >> 8, wh = (w >> 4) & 15, ww = w & 15;
    int tid = threadIdx.x;
    const float* vsrc = s_vp + (w * 6 + n) * 960;
    for (int t = tid; t < 960; t += 256) {
        int m = t / 15, c = t - m * 15;
        vps[m * 16 + c] = vsrc[t];
    }
    if (tid < 64) vps[tid * 16 + 15] = 0.f;
    for (int t = tid; t < 256 * 16; t += 256) {
        int pix = t >> 4, c = t & 15;
        if (c < 15) {
            int gh = wh * 16 + (pix >> 4), gw = ww * 16 + (pix & 15);
            qs[pix * 17 + c] = s_qv[((b * 256 + gh) * 256 + gw) * 180 + n * 15 + c];
        }
    }
    __syncthreads();

    int l = tid;
    float qr[15];
#pragma unroll
    for (int c = 0; c < 15; c++) qr[c] = qs[l * 17 + c];
    u64 qr2[8];
#pragma unroll
    for (int cp = 0; cp < 7; cp++) qr2[cp] = f2pack(qr[2 * cp], qr[2 * cp + 1]);
    qr2[7] = f2pack(qr[14], 0.f);

    u64 out2[8];
#pragma unroll
    for (int cp = 0; cp < 8; cp++) out2[cp] = 0ull;
    const float* rp = s_rpb + n * 16384;   // [m][l]

#pragma unroll
    for (int ch = 0; ch < 4; ch++) {
        float co[16];
#pragma unroll
        for (int mm = 0; mm < 16; mm++) {
            int m = ch * 16 + mm;
            u64 a = 0ull;
#pragma unroll
            for (int cp = 0; cp < 8; cp++)
                a = f2fma(qr2[cp], *(const u64*)(vps + m * 16 + 2 * cp), a);
            co[mm] = f2hadd(a) * (1.0f / 15.0f) + rp[m * 256 + l];
        }
#pragma unroll
        for (int mm = 0; mm < 16; mm++) {
            int m = ch * 16 + mm;
            u64 c2 = f2pack(co[mm], co[mm]);
#pragma unroll
            for (int cp = 0; cp < 8; cp++)
                out2[cp] = f2fma(c2, *(const u64*)(vps + m * 16 + 2 * cp), out2[cp]);
        }
    }
    float o[16];
#pragma unroll
    for (int cp = 0; cp < 8; cp++) f2unpack(out2[cp], o[2 * cp], o[2 * cp + 1]);
#pragma unroll
    for (int c = 0; c < 15; c++) qs[l * 17 + c] = o[c];
    __syncthreads();
    for (int t = tid; t < 256 * 16; t += 256) {
        int pix = t >> 4, c = t & 15;
        if (c < 15) {
            int gh = wh * 16 + (pix >> 4), gw = ww * 16 + (pix & 15);
            s_cat[((b * 256 + gh) * 256 + gw) * 180 + n * 15 + c] = qs[pix * 17 + c];
        }
    }
}

// ================= channel correlation (f32x2) =================
#define QP 258
__global__ __launch_bounds__(512, 1) void k_ch() {
    extern __shared__ float sm[];
    float* q = sm;               // 186 * 258
    float* ccs = sm + 186 * QP;  // 90*90
    int w = blockIdx.x;
    int b = w >> 8, wh = (w >> 4) & 15, ww = w & 15;
    int tid = threadIdx.x;

    for (int t = tid; t < 6 * QP; t += 512) q[180 * QP + t] = 0.f;
    for (int t = tid; t < 256 * 45; t += 512) {
        int l = t / 45, j = t - l * 45;
        int gh = wh * 16 + (l >> 4), gw = ww * 16 + (l & 15);
        float4 v = *(const float4*)(s_qv + ((b * 256 + gh) * 256 + gw) * 180 + j * 4);
        int c = 4 * j;
        q[(c    ) * QP + l] = v.x;
        q[(c + 1) * QP + l] = v.y;
        q[(c + 2) * QP + l] = v.z;
        q[(c + 3) * QP + l] = v.w;
    }
    __syncthreads();

    {
        int wc = tid >> 5, td = tid & 31;
        u64 acc[6][3];
#pragma unroll
        for (int i = 0; i < 6; i++)
#pragma unroll
            for (int j = 0; j < 3; j++) acc[i][j] = 0ull;
        for (int lp = 0; lp < 128; lp++) {
            u64 qa[6], vb[3];
#pragma unroll
            for (int i = 0; i < 6; i++) qa[i] = *(const u64*)(q + (wc + 16 * i) * QP + 2 * lp);
#pragma unroll
            for (int j = 0; j < 3; j++) vb[j] = *(const u64*)(q + (90 + td + 32 * j) * QP + 2 * lp);
#pragma unroll
            for (int i = 0; i < 6; i++)
#pragma unroll
                for (int j = 0; j < 3; j++) acc[i][j] = f2fma(qa[i], vb[j], acc[i][j]);
        }
#pragma unroll
        for (int i = 0; i < 6; i++)
#pragma unroll
            for (int j = 0; j < 3; j++) {
                int c = wc + 16 * i, d = td + 32 * j;
                if (c < 90 && d < 90) ccs[c * 90 + d] = f2hadd(acc[i][j]) * (1.f / 256.f);
            }
    }
    __syncthreads();

    {
        int tl = tid & 31, wc = tid >> 5;
        int ci[6];
#pragma unroll
        for (int jc = 0; jc < 6; jc++) {
            int c = wc + 16 * jc;
            ci[jc] = (c < 90) ? c : 89;
        }
        u64 acc[4][6];
#pragma unroll
        for (int il = 0; il < 4; il++)
#pragma unroll
            for (int jc = 0; jc < 6; jc++) acc[il][jc] = 0ull;
        for (int d = 0; d < 90; d++) {
            u64 vv[4];
#pragma unroll
            for (int il = 0; il < 4; il++)
                vv[il] = *(const u64*)(q + (90 + d) * QP + 2 * (tl + 32 * il));
#pragma unroll
            for (int jc = 0; jc < 6; jc++) {
                float cv = ccs[ci[jc] * 90 + d];
                u64 cvp = f2pack(cv, cv);
#pragma unroll
                for (int il = 0; il < 4; il++) acc[il][jc] = f2fma(vv[il], cvp, acc[il][jc]);
            }
        }
#pragma unroll
        for (int jc = 0; jc < 6; jc++) {
            int c = wc + 16 * jc;
            if (c < 90) {
#pragma unroll
                for (int il = 0; il < 4; il++) {
                    int l0 = 2 * (tl + 32 * il);
                    float a0, a1;
                    f2unpack(acc[il][jc], a0, a1);
                    int gh0 = wh * 16 + (l0 >> 4), gw0 = ww * 16 + (l0 & 15);
                    s_cat[((b * 256 + gh0) * 256 + gw0) * 180 + 90 + c] = a0;
                    int l1 = l0 + 1;
                    int gh1 = wh * 16 + (l1 >> 4), gw1 = ww * 16 + (l1 & 15);
                    s_cat[((b * 256 + gh1) * 256 + gw1) * 180 + 90 + c] = a1;
                }
            }
        }
    }
}

// ============ k_projM: mma.sync tf32 GEMM  out = cat @ Wp + bp ============
#define KP 188
__global__ __launch_bounds__(256, 1) void k_projM(const float* __restrict__ wp,
                                                  const float* __restrict__ bp,
                                                  float* __restrict__ out) {
    extern __shared__ float sm[];
    float* As = sm;                  // 128*188
    float* Bs = As + 128 * KP;       // 64*188
    float* bias_s = Bs + 64 * KP;    // 192
    int tid = threadIdx.x;
    int row0 = blockIdx.x * 128;
    int wid = tid >> 5, lane = tid & 31;

    for (int t = tid; t < 192; t += 256) bias_s[t] = (t < 180) ? bp[t] : 0.f;
    for (int t = tid; t < 128 * 47; t += 256) {
        int r = t / 47, g = t - r * 47;
        unsigned* d = (unsigned*)(As + r * KP + 4 * g);
        if (g < 45) {
            float4 f = *(const float4*)(s_cat + (size_t)(row0 + r) * 180 + 4 * g);
            d[0] = tf32r(f.x); d[1] = tf32r(f.y); d[2] = tf32r(f.z); d[3] = tf32r(f.w);
        } else {
            d[0] = 0u; d[1] = 0u; d[2] = 0u; d[3] = 0u;
        }
    }

    int wm = wid * 16;
    int r1 = lane >> 2, kc = lane & 3;

#pragma unroll 1
    for (int nc = 0; nc < 3; nc++) {
        int nbase = nc * 64;
        __syncthreads();
        for (int t = tid; t < 47 * 64; t += 256) {
            int kq = t >> 6, n = t & 63;
            int col = nbase + n;
            unsigned v0 = 0u, v1 = 0u, v2 = 0u, v3 = 0u;
            if (col < 180) {
                int k = 4 * kq;
                if (k     < 180) v0 = tf32r(wp[(k    ) * 180 + col]);
                if (k + 1 < 180) v1 = tf32r(wp[(k + 1) * 180 + col]);
                if (k + 2 < 180) v2 = tf32r(wp[(k + 2) * 180 + col]);
                if (k + 3 < 180) v3 = tf32r(wp[(k + 3) * 180 + col]);
            }
            unsigned* d = (unsigned*)(Bs + n * KP + 4 * kq);
            d[0] = v0; d[1] = v1; d[2] = v2; d[3] = v3;
        }
        __syncthreads();

        float acc[8][4];
#pragma unroll
        for (int nf = 0; nf < 8; nf++)
#pragma unroll
            for (int j = 0; j < 4; j++) acc[nf][j] = 0.f;

        for (int ks = 0; ks < 23; ks++) {
            int k0 = ks * 8;
            const float* ar = As + (wm + r1) * KP + k0 + kc;
            unsigned a0 = *(const unsigned*)(ar);
            unsigned a1 = *(const unsigned*)(ar + 8 * KP);
            unsigned a2 = *(const unsigned*)(ar + 4);
            unsigned a3 = *(const unsigned*)(ar + 8 * KP + 4);
#pragma unroll
            for (int nf = 0; nf < 8; nf++) {
                const float* br = Bs + (nf * 8 + r1) * KP + k0 + kc;
                unsigned b0 = *(const unsigned*)(br);
                unsigned b1 = *(const unsigned*)(br + 4);
                mma8(acc[nf], a0, a1, a2, a3, b0, b1);
            }
        }

        int cb = 2 * (lane & 3);
#pragma unroll
        for (int nf = 0; nf < 8; nf++) {
            int col = nbase + nf * 8 + cb;
            if (col < 180) {
                int ro = row0 + wm + r1;
                float bx = bias_s[col], by = bias_s[col + 1];
                float2 v0 = make_float2(acc[nf][0] + bx, acc[nf][1] + by);
                *(float2*)(out + (size_t)ro * 180 + col) = v0;
                float2 v1 = make_float2(acc[nf][2] + bx, acc[nf][3] + by);
                *(float2*)(out + (size_t)(ro + 8) * 180 + col) = v1;
            }
        }
    }
}

// ================= launch =================
extern "C" void kernel_launch(void* const* d_in, const int* in_sizes, int n_in,
                              void* d_out, int out_size) {
    const float* x        = (const float*)d_in[0];
    const float* conv1_w  = (const float*)d_in[1];
    const float* conv1_b  = (const float*)d_in[2];
    const float* conv2_w  = (const float*)d_in[3];
    const float* conv2_b  = (const float*)d_in[4];
    const float* conv3_w  = (const float*)d_in[5];
    const float* conv3_b  = (const float*)d_in[6];
    const float* dfe_lw   = (const float*)d_in[7];
    const float* dfe_lb   = (const float*)d_in[8];
    const float* sl_w     = (const float*)d_in[9];
    const float* sl_b     = (const float*)d_in[10];
    const float* pos_w    = (const float*)d_in[11];
    const float* pos_b    = (const float*)d_in[12];
    const float* ln1_g    = (const float*)d_in[13];
    const float* ln1_b    = (const float*)d_in[14];
    const float* mlp1_w   = (const float*)d_in[15];
    const float* mlp1_b   = (const float*)d_in[16];
    const float* ln2_g    = (const float*)d_in[17];
    const float* ln2_b    = (const float*)d_in[18];
    const float* mlp2_w   = (const float*)d_in[19];
    const float* mlp2_b   = (const float*)d_in[20];
    const float* ln3_g    = (const float*)d_in[21];
    const float* ln3_b    = (const float*)d_in[22];
    const float* mlp3_w   = (const float*)d_in[23];
    const float* mlp3_b   = (const float*)d_in[24];
    const float* proj_w   = (const float*)d_in[25];
    const float* proj_b   = (const float*)d_in[26];
    float* out = (float*)d_out;

    const int SM1 = (40 * 182 + 64 * 180) * 4;
    const int SMCV = (18 * 324 * 2 + 9 * 18 * 40 * 2) * 4;
    const int SM3 = (192 * 38 + 192 * 182 + 64 * 180 + 64 * 36) * 4;
    const int SMC = (186 * QP + 90 * 90) * 4;
    const int SMPM = (128 * KP + 64 * KP + 192) * 4;

    cudaFuncSetAttribute(k_dfe1, cudaFuncAttributeMaxDynamicSharedMemorySize, SM1);
    cudaFuncSetAttribute(k_conv, cudaFuncAttributeMaxDynamicSharedMemorySize, SMCV);
    cudaFuncSetAttribute(k_dfe3, cudaFuncAttributeMaxDynamicSharedMemorySize, SM3);
    cudaFuncSetAttribute(k_ch,   cudaFuncAttributeMaxDynamicSharedMemorySize, SMC);
    cudaFuncSetAttribute(k_projM, cudaFuncAttributeMaxDynamicSharedMemorySize, SMPM);

    k_postab<<<4, 256>>>(pos_w, pos_b, ln1_g, ln1_b, mlp1_w, mlp1_b,
                         ln2_g, ln2_b, mlp2_w, mlp2_b, ln3_g, ln3_b, mlp3_w, mlp3_b);
    k_rpb<<<64, 256>>>();
    k_dfe1<<<PTOT / 64, 256, SM1>>>(x, conv1_w, conv1_b);
    k_conv<<<dim3(16, 16, 2), 512, SMCV>>>(conv2_w, conv2_b);
    k_dfe3<<<148, 512, SM3>>>(x, conv3_w, conv3_b, dfe_lw, dfe_lb);
    k_vp<<<(NWIN * 384 * 16 + 255) / 256, 256>>>(sl_w, sl_b);
    k_sp<<<NWIN * 6, 256>>>();
    k_ch<<<NWIN, 512, SMC>>>();
    k_projM<<<PTOT / 128, 256, SMPM>>>(proj_w, proj_b, out);
}

// round 16
// speedup vs baseline: 1.4955x; 1.0143x over previous
#include <cuda_runtime.h>
#include <math.h>

// ---------------- problem constants ----------------
#define BATCH 2
#define HH 256
#define WW_ 256
#define CC 180
#define C5 36
#define NHD 6
#define HD 15
#define L 256
#define ML 64
#define NWIN 512
#define PTOT (BATCH*HH*WW_)

typedef unsigned long long u64;

__device__ __forceinline__ u64 f2pack(float lo, float hi) {
    u64 r; asm("mov.b64 %0, {%1,%2};" : "=l"(r) : "f"(lo), "f"(hi)); return r;
}
__device__ __forceinline__ void f2unpack(u64 v, float& a, float& b) {
    asm("mov.b64 {%0,%1}, %2;" : "=f"(a), "=f"(b) : "l"(v));
}
__device__ __forceinline__ u64 f2fma(u64 a, u64 b, u64 c) {
    u64 d; asm("fma.rn.f32x2 %0, %1, %2, %3;" : "=l"(d) : "l"(a), "l"(b), "l"(c)); return d;
}
__device__ __forceinline__ float f2hadd(u64 v) {
    float a, b; f2unpack(v, a, b); return a + b;
}
__device__ __forceinline__ unsigned tf32r(float x) {
    unsigned r; asm("cvt.rna.tf32.f32 %0, %1;" : "=r"(r) : "f"(x)); return r;
}
__device__ __forceinline__ void mma8(float* c, unsigned a0, unsigned a1, unsigned a2, unsigned a3,
                                     unsigned b0, unsigned b1) {
    asm volatile(
        "mma.sync.aligned.m16n8k8.row.col.f32.tf32.tf32.f32 "
        "{%0,%1,%2,%3}, {%4,%5,%6,%7}, {%8,%9}, {%0,%1,%2,%3};"
        : "+f"(c[0]), "+f"(c[1]), "+f"(c[2]), "+f"(c[3])
        : "r"(a0), "r"(a1), "r"(a2), "r"(a3), "r"(b0), "r"(b1));
}

// ---------------- device scratch ----------------
__device__ float s_y1[PTOT * C5];
__device__ float s_y2[PTOT * C5];
__device__ float s_qv[PTOT * CC];
__device__ float s_cat[PTOT * CC];
__device__ float s_rpb[NHD * L * ML];   // layout: [n][m][l]
__device__ float s_tab[961 * NHD];

// ================= position-bias MLP table (961 x 6) =================
__global__ void k_postab(const float* __restrict__ pw, const float* __restrict__ pb,
                         const float* __restrict__ g1, const float* __restrict__ b1,
                         const float* __restrict__ m1w, const float* __restrict__ m1b,
                         const float* __restrict__ g2, const float* __restrict__ b2,
                         const float* __restrict__ m2w, const float* __restrict__ m2b,
                         const float* __restrict__ g3, const float* __restrict__ b3,
                         const float* __restrict__ m3w, const float* __restrict__ m3b) {
    int t = blockIdx.x * blockDim.x + threadIdx.x;
    if (t >= 961) return;
    int a = t / 31, bcol = t - a * 31;
    float gx = (float)a - 15.f, gy = (float)bcol - 15.f;
    float p[11], q[11];
#pragma unroll
    for (int j = 0; j < 11; j++) p[j] = gx * pw[j] + gy * pw[11 + j] + pb[j];
    {
        float m = 0.f;
#pragma unroll
        for (int j = 0; j < 11; j++) m += p[j];
        m *= (1.f / 11.f);
        float v = 0.f;
#pragma unroll
        for (int j = 0; j < 11; j++) { float d = p[j] - m; v += d * d; }
        v *= (1.f / 11.f);
        float inv = 1.f / sqrtf(v + 1e-5f);
#pragma unroll
        for (int j = 0; j < 11; j++) {
            float h = (p[j] - m) * inv * g1[j] + b1[j];
            q[j] = h > 0.f ? h : 0.f;
        }
#pragma unroll
        for (int j = 0; j < 11; j++) {
            float acc = m1b[j];
#pragma unroll
            for (int k = 0; k < 11; k++) acc += q[k] * m1w[k * 11 + j];
            p[j] = acc;
        }
    }
    {
        float m = 0.f;
#pragma unroll
        for (int j = 0; j < 11; j++) m += p[j];
        m *= (1.f / 11.f);
        float v = 0.f;
#pragma unroll
        for (int j = 0; j < 11; j++) { float d = p[j] - m; v += d * d; }
        v *= (1.f / 11.f);
        float inv = 1.f / sqrtf(v + 1e-5f);
#pragma unroll
        for (int j = 0; j < 11; j++) {
            float h = (p[j] - m) * inv * g2[j] + b2[j];
            q[j] = h > 0.f ? h : 0.f;
        }
#pragma unroll
        for (int j = 0; j < 11; j++) {
            float acc = m2b[j];
#pragma unroll
            for (int k = 0; k < 11; k++) acc += q[k] * m2w[k * 11 + j];
            p[j] = acc;
        }
    }
    {
        float m = 0.f;
#pragma unroll
        for (int j = 0; j < 11; j++) m += p[j];
        m *= (1.f / 11.f);
        float v = 0.f;
#pragma unroll
        for (int j = 0; j < 11; j++) { float d = p[j] - m; v += d * d; }
        v *= (1.f / 11.f);
        float inv = 1.f / sqrtf(v + 1e-5f);
#pragma unroll
        for (int j = 0; j < 11; j++) {
            float h = (p[j] - m) * inv * g3[j] + b3[j];
            q[j] = h > 0.f ? h : 0.f;
        }
#pragma unroll
        for (int n = 0; n < 6; n++) {
            float acc = m3b[n];
#pragma unroll
            for (int k = 0; k < 11; k++) acc += q[k] * m3w[k * 6 + n];
            s_tab[t * 6 + n] = acc;
        }
    }
}

// ================= rpb gather/average (transposed [n][m][l]) =================
__global__ void k_rpb() {
    int u = blockIdx.x * blockDim.x + threadIdx.x;
    int m = u >> 8, i = u & 255;
    int hi = i >> 4, wi = i & 15;
    int mh = m >> 3, mw = m & 7;
    float acc[6] = {0.f, 0.f, 0.f, 0.f, 0.f, 0.f};
#pragma unroll
    for (int rh = 0; rh < 2; rh++)
#pragma unroll
        for (int rw = 0; rw < 2; rw++) {
            int jh = mh * 2 + rh, jw = mw * 2 + rw;
            int idx = (hi - jh + 15) * 31 + (wi - jw + 15);
            const float* tr = s_tab + idx * 6;
#pragma unroll
            for (int n = 0; n < 6; n++) acc[n] += tr[n];
        }
#pragma unroll
    for (int n = 0; n < 6; n++) s_rpb[n * 16384 + m * 256 + i] = acc[n] * 0.25f;
}

// ================= DFE stage 1 (f32x2) =================
__global__ __launch_bounds__(256, 3) void k_dfe1(const float* __restrict__ x,
                                                 const float* __restrict__ w,
                                                 const float* __restrict__ b) {
    extern __shared__ float sm[];
    float* w1t = sm;              // 40*182
    float* xs  = sm + 40 * 182;   // 64*180
    int row0 = blockIdx.x * 64;
    int tid = threadIdx.x;
    for (int t = tid; t < 90 * 40; t += 256) {
        int kp = t / 40, c = t - kp * 40;
        float a = 0.f, bb = 0.f;
        if (c < 36) { a = w[(2 * kp) * 36 + c]; bb = w[(2 * kp + 1) * 36 + c]; }
        w1t[c * 182 + 2 * kp] = a;
        w1t[c * 182 + 2 * kp + 1] = bb;
    }
    {
        const float4* src = (const float4*)(x + row0 * 180);
        float4* dst = (float4*)xs;
        for (int t = tid; t < 64 * 45; t += 256) dst[t] = src[t];
    }
    __syncthreads();

    int tr = tid >> 3, tc = tid & 7;
    int r0 = tr * 2, c0 = tc * 5;
    u64 acc[2][5];
#pragma unroll
    for (int i = 0; i < 2; i++)
#pragma unroll
        for (int j = 0; j < 5; j++) acc[i][j] = 0ull;
    for (int kp = 0; kp < 90; kp++) {
        u64 av[2], bv[5];
#pragma unroll
        for (int i = 0; i < 2; i++) av[i] = *(const u64*)(xs + (r0 + i) * 180 + 2 * kp);
#pragma unroll
        for (int j = 0; j < 5; j++) bv[j] = *(const u64*)(w1t + (c0 + j) * 182 + 2 * kp);
#pragma unroll
        for (int i = 0; i < 2; i++)
#pragma unroll
            for (int j = 0; j < 5; j++) acc[i][j] = f2fma(av[i], bv[j], acc[i][j]);
    }
#pragma unroll
    for (int j = 0; j < 5; j++) {
        int c = c0 + j;
        if (c < 36) {
            float bc = b[c];
#pragma unroll
            for (int i = 0; i < 2; i++) {
                float v = f2hadd(acc[i][j]) + bc;
                s_y1[(row0 + r0 + i) * 36 + c] = v > 0.f ? v : 0.2f * v;
            }
        }
    }
}

// ================= DFE stage 2: 3x3 conv, f32x2, 4 px/thread (32x16 tile) =================
__global__ __launch_bounds__(512, 1) void k_conv(const float* __restrict__ w,
                                                 const float* __restrict__ bias) {
    extern __shared__ float sm[];
    float2* hsp = (float2*)sm;                       // 18 kp * 612 halo px
    float2* wt  = (float2*)(sm + 18 * 612 * 2);      // 9*18*40 f2
    int bImg = blockIdx.z, ty = blockIdx.y, tx = blockIdx.x;
    int tid = threadIdx.x;
    int y0 = ty * 16 - 1, x0 = tx * 32 - 1;

    // halo load: 612 px (18 rows x 34 cols) x 18 channel-pairs
    for (int t = tid; t < 612 * 18; t += 512) {
        int hp = t / 18, kp = t - hp * 18;
        int py = hp / 34, px = hp - py * 34;
        int gy = y0 + py, gx = x0 + px;
        float2 v = make_float2(0.f, 0.f);
        if (gy >= 0 && gy < 256 && gx >= 0 && gx < 256)
            v = *(const float2*)(s_y1 + ((bImg * 256 + gy) * 256 + gx) * 36 + 2 * kp);
        hsp[kp * 612 + hp] = v;
    }
    for (int t = tid; t < 9 * 18 * 36; t += 512) {
        int tap = t / (18 * 36);
        int r = t - tap * (18 * 36);
        int kp = r / 36, c = r - kp * 36;
        int cg = c / 9, jc = c - cg * 9;
        wt[(tap * 18 + kp) * 40 + cg * 10 + jc] =
            make_float2(w[(tap * 36 + 2 * kp) * 36 + c], w[(tap * 36 + 2 * kp + 1) * 36 + c]);
    }
    __syncthreads();

    int cg = tid >> 7;          // 0..3 warp-uniform
    int pp = tid & 127;
    int co0 = cg * 9;
    int hb[4];
#pragma unroll
    for (int i = 0; i < 4; i++) {
        int p = pp + 128 * i;
        hb[i] = (p >> 5) * 34 + (p & 31);
    }

    u64 acc[4][9];
#pragma unroll
    for (int ip = 0; ip < 4; ip++)
#pragma unroll
        for (int jc = 0; jc < 9; jc++) acc[ip][jc] = 0ull;

    for (int tap = 0; tap < 9; tap++) {
        int kh = tap / 3, kw = tap - 3 * kh;
        int off = kh * 34 + kw;
        const float2* wrow = wt + tap * 18 * 40 + cg * 10;
#pragma unroll 3
        for (int kp = 0; kp < 18; kp++) {
            const float2* hrow = hsp + kp * 612 + off;
            u64 v0 = *(const u64*)(hrow + hb[0]);
            u64 v1 = *(const u64*)(hrow + hb[1]);
            u64 v2 = *(const u64*)(hrow + hb[2]);
            u64 v3 = *(const u64*)(hrow + hb[3]);
            const float2* wr = wrow + kp * 40;
#pragma unroll
            for (int jc = 0; jc < 9; jc++) {
                u64 wv = *(const u64*)(wr + jc);
                acc[0][jc] = f2fma(v0, wv, acc[0][jc]);
                acc[1][jc] = f2fma(v1, wv, acc[1][jc]);
                acc[2][jc] = f2fma(v2, wv, acc[2][jc]);
                acc[3][jc] = f2fma(v3, wv, acc[3][jc]);
            }
        }
    }

#pragma unroll
    for (int ip = 0; ip < 4; ip++) {
        int p = pp + 128 * ip;
        int py = p >> 5, px = p & 31;
        int gaddr = ((bImg * 256 + ty * 16 + py) * 256 + tx * 32 + px) * 36;
#pragma unroll
        for (int jc = 0; jc < 9; jc++) {
            float v = f2hadd(acc[ip][jc]) + bias[co0 + jc];
            s_y2[gaddr + co0 + jc] = v > 0.f ? v : 0.2f * v;
        }
    }
}

// ============ DFE stage 3 (PERSISTENT, f32x2, fused) ============
__global__ __launch_bounds__(512, 1) void k_dfe3(const float* __restrict__ x,
                                                 const float* __restrict__ w3, const float* __restrict__ b3,
                                                 const float* __restrict__ wl, const float* __restrict__ bl) {
    extern __shared__ float sm[];
    float* w3t = sm;                  // 192*38
    float* wlt = w3t + 192 * 38;      // 192*182
    float* xs  = wlt + 192 * 182;     // 64*180
    float* y2s = xs + 64 * 180;       // 64*36
    int tid = threadIdx.x;
    for (int t = tid; t < 192 * 19; t += 512) {
        int c = t / 19, kp = t - c * 19;
        float a = 0.f, bb = 0.f;
        if (c < 180 && kp < 18) { a = w3[(2 * kp) * 180 + c]; bb = w3[(2 * kp + 1) * 180 + c]; }
        w3t[2 * t] = a; w3t[2 * t + 1] = bb;
    }
    for (int t = tid; t < 192 * 91; t += 512) {
        int c = t / 91, kp = t - c * 91;
        float a = 0.f, bb = 0.f;
        if (c < 180 && kp < 90) { a = wl[(2 * kp) * 180 + c]; bb = wl[(2 * kp + 1) * 180 + c]; }
        wlt[2 * t] = a; wlt[2 * t + 1] = bb;
    }
    int warp = tid >> 5, lane = tid & 31;
    int r0 = warp * 4;
    int cidx[6]; float bcr[6], dcr[6];
#pragma unroll
    for (int j = 0; j < 6; j++) {
        int c = lane + 32 * j; cidx[j] = c;
        bcr[j] = (c < 180) ? b3[c] : 0.f;
        dcr[j] = (c < 180) ? bl[c] : 0.f;
    }

    for (int tile = blockIdx.x; tile < PTOT / 64; tile += gridDim.x) {
        int row0 = tile * 64;
        __syncthreads();
        {
            const float4* src = (const float4*)(x + row0 * 180);
            float4* dst = (float4*)xs;
            for (int t = tid; t < 64 * 45; t += 512) dst[t] = src[t];
            const float4* ys = (const float4*)(s_y2 + row0 * 36);
            float4* yd = (float4*)y2s;
            for (int t = tid; t < 64 * 9; t += 512) yd[t] = ys[t];
        }
        __syncthreads();

        u64 accA[4][6];
#pragma unroll
        for (int i = 0; i < 4; i++)
#pragma unroll
            for (int j = 0; j < 6; j++) accA[i][j] = 0ull;
        for (int kp = 0; kp < 18; kp++) {
            u64 av[4], bv[6];
#pragma unroll
            for (int i = 0; i < 4; i++) av[i] = *(const u64*)(y2s + (r0 + i) * 36 + 2 * kp);
#pragma unroll
            for (int j = 0; j < 6; j++) bv[j] = *(const u64*)(w3t + cidx[j] * 38 + 2 * kp);
#pragma unroll
            for (int i = 0; i < 4; i++)
#pragma unroll
                for (int j = 0; j < 6; j++) accA[i][j] = f2fma(av[i], bv[j], accA[i][j]);
        }
        float aA[4][6];
#pragma unroll
        for (int i = 0; i < 4; i++)
#pragma unroll
            for (int j = 0; j < 6; j++) aA[i][j] = f2hadd(accA[i][j]) + bcr[j];

        u64 accD[4][6];
#pragma unroll
        for (int i = 0; i < 4; i++)
#pragma unroll
            for (int j = 0; j < 6; j++) accD[i][j] = 0ull;
        for (int kp = 0; kp < 90; kp++) {
            u64 av[4], bv[6];
#pragma unroll
            for (int i = 0; i < 4; i++) av[i] = *(const u64*)(xs + (r0 + i) * 180 + 2 * kp);
#pragma unroll
            for (int j = 0; j < 6; j++) bv[j] = *(const u64*)(wlt + cidx[j] * 182 + 2 * kp);
#pragma unroll
            for (int i = 0; i < 4; i++)
#pragma unroll
                for (int j = 0; j < 6; j++) accD[i][j] = f2fma(av[i], bv[j], accD[i][j]);
        }
#pragma unroll
        for (int j = 0; j < 6; j++) {
            int c = cidx[j];
            if (c < 180) {
#pragma unroll
                for (int i = 0; i < 4; i++)
                    s_qv[(row0 + r0 + i) * 180 + c] = aA[i][j] * (f2hadd(accD[i][j]) + dcr[j]);
            }
        }
    }
}

// ================= spatial correlation (f32x2, vp fused, staged I/O) =================
__global__ __launch_bounds__(256, 3) void k_sp(const float* __restrict__ sl_w,
                                               const float* __restrict__ sl_b) {
    __shared__ float vps[64 * 16];
    __shared__ float qs[256 * 17];
    int blk = blockIdx.x;
    int w = blk / 6, n = blk - w * 6;
    int b = w >> 8, wh = (w >> 4) & 15, ww = w & 15;
    int tid = threadIdx.x;
    float w0 = sl_w[0], w1 = sl_w[1], w2 = sl_w[2], w3 = sl_w[3], bb = sl_b[0];

    // fused vp: compute downsampled v directly from s_qv
    for (int t = tid; t < 960; t += 256) {
        int m = t / 15, c = t - m * 15;
        int mh = m >> 3, mw = m & 7;
        int gh = wh * 16 + mh * 2, gw = ww * 16 + mw * 2;
        const float* q00 = s_qv + ((b * 256 + gh) * 256 + gw) * 180 + 90 + n * 15;
        vps[m * 16 + c] = bb + q00[c] * w0 + q00[180 + c] * w1
                             + q00[256 * 180 + c] * w2 + q00[256 * 180 + 180 + c] * w3;
    }
    if (tid < 64) vps[tid * 16 + 15] = 0.f;
    for (int t = tid; t < 256 * 16; t += 256) {
        int pix = t >> 4, c = t & 15;
        if (c < 15) {
            int gh = wh * 16 + (pix >> 4), gw = ww * 16 + (pix & 15);
            qs[pix * 17 + c] = s_qv[((b * 256 + gh) * 256 + gw) * 180 + n * 15 + c];
        }
    }
    __syncthreads();

    int l = tid;
    float qr[15];
#pragma unroll
    for (int c = 0; c < 15; c++) qr[c] = qs[l * 17 + c];
    u64 qr2[8];
#pragma unroll
    for (int cp = 0; cp < 7; cp++) qr2[cp] = f2pack(qr[2 * cp], qr[2 * cp + 1]);
    qr2[7] = f2pack(qr[14], 0.f);

    u64 out2[8];
#pragma unroll
    for (int cp = 0; cp < 8; cp++) out2[cp] = 0ull;
    const float* rp = s_rpb + n * 16384;   // [m][l]

#pragma unroll
    for (int ch = 0; ch < 4; ch++) {
        float co[16];
#pragma unroll
        for (int mm = 0; mm < 16; mm++) {
            int m = ch * 16 + mm;
            u64 a = 0ull;
#pragma unroll
            for (int cp = 0; cp < 8; cp++)
                a = f2fma(qr2[cp], *(const u64*)(vps + m * 16 + 2 * cp), a);
            co[mm] = f2hadd(a) * (1.0f / 15.0f) + rp[m * 256 + l];
        }
#pragma unroll
        for (int mm = 0; mm < 16; mm++) {
            int m = ch * 16 + mm;
            u64 c2 = f2pack(co[mm], co[mm]);
#pragma unroll
            for (int cp = 0; cp < 8; cp++)
                out2[cp] = f2fma(c2, *(const u64*)(vps + m * 16 + 2 * cp), out2[cp]);
        }
    }
    float o[16];
#pragma unroll
    for (int cp = 0; cp < 8; cp++) f2unpack(out2[cp], o[2 * cp], o[2 * cp + 1]);
#pragma unroll
    for (int c = 0; c < 15; c++) qs[l * 17 + c] = o[c];
    __syncthreads();
    for (int t = tid; t < 256 * 16; t += 256) {
        int pix = t >> 4, c = t & 15;
        if (c < 15) {
            int gh = wh * 16 + (pix >> 4), gw = ww * 16 + (pix & 15);
            s_cat[((b * 256 + gh) * 256 + gw) * 180 + n * 15 + c] = qs[pix * 17 + c];
        }
    }
}

// ================= channel correlation (f32x2; phase-2 lane=channel, coalesced stores) =================
#define QP 258
__global__ __launch_bounds__(512, 1) void k_ch() {
    extern __shared__ float sm[];
    float* q = sm;               // 186 * 258
    float* ccs = sm + 186 * QP;  // 90*90
    int w = blockIdx.x;
    int b = w >> 8, wh = (w >> 4) & 15, ww = w & 15;
    int tid = threadIdx.x;

    for (int t = tid; t < 6 * QP; t += 512) q[180 * QP + t] = 0.f;
    for (int t = tid; t < 256 * 45; t += 512) {
        int l = t / 45, j = t - l * 45;
        int gh = wh * 16 + (l >> 4), gw = ww * 16 + (l & 15);
        float4 v = *(const float4*)(s_qv + ((b * 256 + gh) * 256 + gw) * 180 + j * 4);
        int c = 4 * j;
        q[(c    ) * QP + l] = v.x;
        q[(c + 1) * QP + l] = v.y;
        q[(c + 2) * QP + l] = v.z;
        q[(c + 3) * QP + l] = v.w;
    }
    __syncthreads();

    // phase 1: cc[c][d] (pair over l)
    {
        int wc = tid >> 5, td = tid & 31;
        u64 acc[6][3];
#pragma unroll
        for (int i = 0; i < 6; i++)
#pragma unroll
            for (int j = 0; j < 3; j++) acc[i][j] = 0ull;
        for (int lp = 0; lp < 128; lp++) {
            u64 qa[6], vb[3];
#pragma unroll
            for (int i = 0; i < 6; i++) qa[i] = *(const u64*)(q + (wc + 16 * i) * QP + 2 * lp);
#pragma unroll
            for (int j = 0; j < 3; j++) vb[j] = *(const u64*)(q + (90 + td + 32 * j) * QP + 2 * lp);
#pragma unroll
            for (int i = 0; i < 6; i++)
#pragma unroll
                for (int j = 0; j < 3; j++) acc[i][j] = f2fma(qa[i], vb[j], acc[i][j]);
        }
#pragma unroll
        for (int i = 0; i < 6; i++)
#pragma unroll
            for (int j = 0; j < 3; j++) {
                int c = wc + 16 * i, d = td + 32 * j;
                if (c < 90 && d < 90) ccs[c * 90 + d] = f2hadd(acc[i][j]) * (1.f / 256.f);
            }
    }
    __syncthreads();

    // phase 2: x_ch[l][c] = sum_d cc[c][d] v[l][d]; warp=16 l rows, lane=c
    {
        int warp = tid >> 5, lane = tid & 31;
        int l0 = warp * 16;
        int ci[3];
#pragma unroll
        for (int j = 0; j < 3; j++) {
            int c = lane + 32 * j;
            ci[j] = (c < 90) ? c : 89;
        }
        float acc[16][3];
#pragma unroll
        for (int il = 0; il < 16; il++)
#pragma unroll
            for (int j = 0; j < 3; j++) acc[il][j] = 0.f;
        for (int dp = 0; dp < 45; dp++) {
            int d = 2 * dp;
            u64 cvp[3];
#pragma unroll
            for (int j = 0; j < 3; j++) cvp[j] = *(const u64*)(ccs + ci[j] * 90 + d);
            const float* vr0 = q + (90 + d) * QP;
            const float* vr1 = q + (90 + d + 1) * QP;
#pragma unroll
            for (int il = 0; il < 16; il++) {
                u64 vp2 = f2pack(vr0[l0 + il], vr1[l0 + il]);
#pragma unroll
                for (int j = 0; j < 3; j++) {
                    u64 t2 = f2fma(vp2, cvp[j], 0ull);
                    float x0, x1; f2unpack(t2, x0, x1);
                    acc[il][j] += x0 + x1;
                }
            }
        }
#pragma unroll
        for (int j = 0; j < 3; j++) {
            int c = lane + 32 * j;
            if (c < 90) {
#pragma unroll
                for (int il = 0; il < 16; il++) {
                    int l = l0 + il;
                    int gh = wh * 16 + (l >> 4), gw = ww * 16 + (l & 15);
                    s_cat[((b * 256 + gh) * 256 + gw) * 180 + 90 + c] = acc[il][j];
                }
            }
        }
    }
}

// ============ k_projM: mma.sync tf32 GEMM  out = cat @ Wp + bp ============
#define KP 188
__global__ __launch_bounds__(256, 1) void k_projM(const float* __restrict__ wp,
                                                  const float* __restrict__ bp,
                                                  float* __restrict__ out) {
    extern __shared__ float sm[];
    float* As = sm;                  // 128*188
    float* Bs = As + 128 * KP;       // 64*188
    float* bias_s = Bs + 64 * KP;    // 192
    int tid = threadIdx.x;
    int row0 = blockIdx.x * 128;
    int wid = tid >> 5, lane = tid & 31;

    for (int t = tid; t < 192; t += 256) bias_s[t] = (t < 180) ? bp[t] : 0.f;
    for (int t = tid; t < 128 * 47; t += 256) {
        int r = t / 47, g = t - r * 47;
        unsigned* d = (unsigned*)(As + r * KP + 4 * g);
        if (g < 45) {
            float4 f = *(const float4*)(s_cat + (size_t)(row0 + r) * 180 + 4 * g);
            d[0] = tf32r(f.x); d[1] = tf32r(f.y); d[2] = tf32r(f.z); d[3] = tf32r(f.w);
        } else {
            d[0] = 0u; d[1] = 0u; d[2] = 0u; d[3] = 0u;
        }
    }

    int wm = wid * 16;
    int r1 = lane >> 2, kc = lane & 3;

#pragma unroll 1
    for (int nc = 0; nc < 3; nc++) {
        int nbase = nc * 64;
        __syncthreads();
        for (int t = tid; t < 47 * 64; t += 256) {
            int kq = t >> 6, n = t & 63;
            int col = nbase + n;
            unsigned v0 = 0u, v1 = 0u, v2 = 0u, v3 = 0u;
            if (col < 180) {
                int k = 4 * kq;
                if (k     < 180) v0 = tf32r(wp[(k    ) * 180 + col]);
                if (k + 1 < 180) v1 = tf32r(wp[(k + 1) * 180 + col]);
                if (k + 2 < 180) v2 = tf32r(wp[(k + 2) * 180 + col]);
                if (k + 3 < 180) v3 = tf32r(wp[(k + 3) * 180 + col]);
            }
            unsigned* d = (unsigned*)(Bs + n * KP + 4 * kq);
            d[0] = v0; d[1] = v1; d[2] = v2; d[3] = v3;
        }
        __syncthreads();

        float acc[8][4];
#pragma unroll
        for (int nf = 0; nf < 8; nf++)
#pragma unroll
            for (int j = 0; j < 4; j++) acc[nf][j] = 0.f;

        for (int ks = 0; ks < 23; ks++) {
            int k0 = ks * 8;
            const float* ar = As + (wm + r1) * KP + k0 + kc;
            unsigned a0 = *(const unsigned*)(ar);
            unsigned a1 = *(const unsigned*)(ar + 8 * KP);
            unsigned a2 = *(const unsigned*)(ar + 4);
            unsigned a3 = *(const unsigned*)(ar + 8 * KP + 4);
#pragma unroll
            for (int nf = 0; nf < 8; nf++) {
                const float* br = Bs + (nf * 8 + r1) * KP + k0 + kc;
                unsigned b0 = *(const unsigned*)(br);
                unsigned b1 = *(const unsigned*)(br + 4);
                mma8(acc[nf], a0, a1, a2, a3, b0, b1);
            }
        }

        int cb = 2 * (lane & 3);
#pragma unroll
        for (int nf = 0; nf < 8; nf++) {
            int col = nbase + nf * 8 + cb;
            if (col < 180) {
                int ro = row0 + wm + r1;
                float bx = bias_s[col], by = bias_s[col + 1];
                float2 v0 = make_float2(acc[nf][0] + bx, acc[nf][1] + by);
                *(float2*)(out + (size_t)ro * 180 + col) = v0;
                float2 v1 = make_float2(acc[nf][2] + bx, acc[nf][3] + by);
                *(float2*)(out + (size_t)(ro + 8) * 180 + col) = v1;
            }
        }
    }
}

// ================= launch =================
extern "C" void kernel_launch(void* const* d_in, const int* in_sizes, int n_in,
                              void* d_out, int out_size) {
    const float* x        = (const float*)d_in[0];
    const float* conv1_w  = (const float*)d_in[1];
    const float* conv1_b  = (const float*)d_in[2];
    const float* conv2_w  = (const float*)d_in[3];
    const float* conv2_b  = (const float*)d_in[4];
    const float* conv3_w  = (const float*)d_in[5];
    const float* conv3_b  = (const float*)d_in[6];
    const float* dfe_lw   = (const float*)d_in[7];
    const float* dfe_lb   = (const float*)d_in[8];
    const float* sl_w     = (const float*)d_in[9];
    const float* sl_b     = (const float*)d_in[10];
    const float* pos_w    = (const float*)d_in[11];
    const float* pos_b    = (const float*)d_in[12];
    const float* ln1_g    = (const float*)d_in[13];
    const float* ln1_b    = (const float*)d_in[14];
    const float* mlp1_w   = (const float*)d_in[15];
    const float* mlp1_b   = (const float*)d_in[16];
    const float* ln2_g    = (const float*)d_in[17];
    const float* ln2_b    = (const float*)d_in[18];
    const float* mlp2_w   = (const float*)d_in[19];
    const float* mlp2_b   = (const float*)d_in[20];
    const float* ln3_g    = (const float*)d_in[21];
    const float* ln3_b    = (const float*)d_in[22];
    const float* mlp3_w   = (const float*)d_in[23];
    const float* mlp3_b   = (const float*)d_in[24];
    const float* proj_w   = (const float*)d_in[25];
    const float* proj_b   = (const float*)d_in[26];
    float* out = (float*)d_out;

    const int SM1 = (40 * 182 + 64 * 180) * 4;
    const int SMCV = (18 * 612 * 2 + 9 * 18 * 40 * 2) * 4;     // 139,968
    const int SM3 = (192 * 38 + 192 * 182 + 64 * 180 + 64 * 36) * 4;
    const int SMC = (186 * QP + 90 * 90) * 4;
    const int SMPM = (128 * KP + 64 * KP + 192) * 4;

    cudaFuncSetAttribute(k_dfe1, cudaFuncAttributeMaxDynamicSharedMemorySize, SM1);
    cudaFuncSetAttribute(k_conv, cudaFuncAttributeMaxDynamicSharedMemorySize, SMCV);
    cudaFuncSetAttribute(k_dfe3, cudaFuncAttributeMaxDynamicSharedMemorySize, SM3);
    cudaFuncSetAttribute(k_ch,   cudaFuncAttributeMaxDynamicSharedMemorySize, SMC);
    cudaFuncSetAttribute(k_projM, cudaFuncAttributeMaxDynamicSharedMemorySize, SMPM);

    k_postab<<<4, 256>>>(pos_w, pos_b, ln1_g, ln1_b, mlp1_w, mlp1_b,
                         ln2_g, ln2_b, mlp2_w, mlp2_b, ln3_g, ln3_b, mlp3_w, mlp3_b);
    k_rpb<<<64, 256>>>();
    k_dfe1<<<PTOT / 64, 256, SM1>>>(x, conv1_w, conv1_b);
    k_conv<<<dim3(8, 16, 2), 512, SMCV>>>(conv2_w, conv2_b);
    k_dfe3<<<148, 512, SM3>>>(x, conv3_w, conv3_b, dfe_lw, dfe_lb);
    k_sp<<<NWIN * 6, 256>>>(sl_w, sl_b);
    k_ch<<<NWIN, 512, SMC>>>();
    k_projM<<<PTOT / 128, 256, SMPM>>>(proj_w, proj_b, out);
}